// round 15
// baseline (speedup 1.0000x reference)
#include <cuda_runtime.h>
#include <cuda_bf16.h>
#include <math.h>
typedef unsigned long long ull;
typedef __nv_bfloat16 bf16;

#define VOCAB 10000
#define VPAD  10048
#define H 1024
#define H2 2048
#define BB 32
#define TT 128
#define MROWS (BB*TT)
#define NB 64
#define NTHR 256

// rnn smem (bytes): chunk=128; A plane 32x272=8704, buf(hi+lo)=17408; W buf 64rows=34816
#define PLB  8704
#define BUFB 17408
#define WBUF 34816
#define SA   0
#define SA1  52224
#define SW   104448
#define SRED 208896
#define RSM  217088

// hgemm smem (bytes)
#define HA_L 18432
#define HB_H 36864
#define HB_L 46080
#define HBUF 55296
#define HSM  (2*HBUF)

// ---------------- device scratch ----------------
__device__ __align__(16) float g_gx0[(size_t)TT*BB*H2];   // [t][m][n]
__device__ __align__(16) float g_cx0[(size_t)TT*BB*H];
__device__ __align__(16) float g_outT[(size_t)TT*BB*H];
__device__ __align__(16) float g_h0m[2][BB*H];
__device__ __align__(16) float g_h1m[BB*H];
__device__ __align__(16) float g_u0m[BB*H];
__device__ __align__(16) float g_u1m[BB*H];
__device__ __align__(16) bf16 g_h0h[2][BB*H], g_h0l[2][BB*H];
__device__ __align__(16) bf16 g_h1h[BB*H],  g_h1l[BB*H];
__device__ __align__(16) bf16 g_rh0h[BB*H], g_rh0l[BB*H];
__device__ __align__(16) bf16 g_rh1h[BB*H], g_rh1l[BB*H];
__device__ __align__(16) bf16 g_wgt0h[(size_t)H2*H],  g_wgt0l[(size_t)H2*H];
__device__ __align__(16) bf16 g_wgt1h[(size_t)H2*H2], g_wgt1l[(size_t)H2*H2];
__device__ __align__(16) bf16 g_wct0h[(size_t)H*H],   g_wct0l[(size_t)H*H];
__device__ __align__(16) bf16 g_wct1h[(size_t)H*H2],  g_wct1l[(size_t)H*H2];
__device__ __align__(16) bf16 g_xh[(size_t)MROWS*H], g_xl[(size_t)MROWS*H];
__device__ __align__(16) bf16 g_oh[(size_t)MROWS*H], g_ol[(size_t)MROWS*H];
__device__ __align__(16) bf16 g_wgh[(size_t)H2*H],  g_wgl[(size_t)H2*H];
__device__ __align__(16) bf16 g_wch[(size_t)H*H],   g_wcl[(size_t)H*H];
__device__ __align__(16) bf16 g_eh[(size_t)VPAD*H], g_el[(size_t)VPAD*H];
__device__ volatile unsigned g_cnt;
__device__ volatile unsigned g_gen;

// ---------------- helpers ----------------
__device__ __forceinline__ float sigf(float x){ return __fdividef(1.f, 1.f+__expf(-x)); }
__device__ __forceinline__ float tanhx(float x){ return 1.f-__fdividef(2.f, __expf(2.f*x)+1.f); }

__device__ __forceinline__ void cp16(void* d, const void* s){
    unsigned ds = (unsigned)__cvta_generic_to_shared(d);
    asm volatile("cp.async.cg.shared.global [%0], [%1], 16;" :: "r"(ds), "l"(s) : "memory");
}
#define CP_COMMIT asm volatile("cp.async.commit_group;" ::: "memory")
#define CP_WAIT0  asm volatile("cp.async.wait_group 0;" ::: "memory")
#define CP_WAIT1  asm volatile("cp.async.wait_group 1;" ::: "memory")

__device__ __forceinline__ void gsync(){
    __threadfence();
    __syncthreads();
    if (threadIdx.x == 0){
        unsigned gen = g_gen;
        unsigned old = atomicAdd((unsigned*)&g_cnt, 1u);
        if (old == NB-1){ g_cnt = 0; __threadfence(); g_gen = gen+1; }
        else { while (g_gen == gen) { __nanosleep(40); } }
    }
    __syncthreads();
}

__device__ __forceinline__ void ldm4(unsigned& r0, unsigned& r1, unsigned& r2, unsigned& r3,
                                     unsigned addr){
    asm volatile("ldmatrix.sync.aligned.m8n8.x4.shared.b16 {%0,%1,%2,%3}, [%4];"
        : "=r"(r0), "=r"(r1), "=r"(r2), "=r"(r3) : "r"(addr));
}
__device__ __forceinline__ void mma16816(float* c, const unsigned* a, const unsigned* b){
    asm volatile("mma.sync.aligned.m16n8k16.row.col.f32.bf16.bf16.f32 "
        "{%0,%1,%2,%3},{%4,%5,%6,%7},{%8,%9},{%0,%1,%2,%3};"
        : "+f"(c[0]), "+f"(c[1]), "+f"(c[2]), "+f"(c[3])
        : "r"(a[0]), "r"(a[1]), "r"(a[2]), "r"(a[3]), "r"(b[0]), "r"(b[1]));
}
__device__ __forceinline__ void wsplit(float v, bf16* hp, bf16* lp, size_t o){
    bf16 h = __float2bfloat16(v);
    hp[o] = h; lp[o] = __float2bfloat16(v - __bfloat162float(h));
}

// ---------------- prep kernels (r14, unchanged) ----------------
__global__ void prep_wq(const float* __restrict__ Wg0, const float* __restrict__ Wg1,
                        const float* __restrict__ Wc0, const float* __restrict__ Wc1){
    __shared__ float s[32][33];
    int b = blockIdx.x;
    const float* src; bf16 *dh, *dl; int srow0, ld, ldd, bx, by;
    if (b < 2048){      src=Wg0; srow0=1024; ld=H2; dh=g_wgt0h; dl=g_wgt0l; ldd=H;  bx=b&31; by=b>>5; }
    else if (b<6144){ int q=b-2048; src=Wg1; srow0=0; ld=H2; dh=g_wgt1h; dl=g_wgt1l; ldd=H2; bx=q&63; by=q>>6; }
    else if (b<7168){ int q=b-6144; src=Wc0; srow0=1024; ld=H; dh=g_wct0h; dl=g_wct0l; ldd=H; bx=q&31; by=q>>5; }
    else {            int q=b-7168; src=Wc1; srow0=0; ld=H; dh=g_wct1h; dl=g_wct1l; ldd=H2; bx=q&63; by=q>>6; }
    int kb = bx*32, nb = by*32;
    int t = threadIdx.x, tx = t&31, ty = t>>5;
#pragma unroll
    for (int i=0;i<32;i+=8) s[ty+i][tx] = src[(size_t)(srow0+kb+ty+i)*ld + nb+tx];
    __syncthreads();
#pragma unroll
    for (int i=0;i<32;i+=8)
        wsplit(s[tx][ty+i], dh, dl, (size_t)(nb+ty+i)*ldd + kb+tx);
}

__global__ void prep_cv(const int* __restrict__ idx, const float* __restrict__ emb,
                        const float* __restrict__ Wg0, const float* __restrict__ Wc0){
    __shared__ float s[32][33];
    int b = blockIdx.x, t = threadIdx.x;
    if (b < 4096){
        float4 v = ((const float4*)(emb + (size_t)idx[b]*H))[t];
        float a[4] = {v.x,v.y,v.z,v.w};
        size_t o = (size_t)b*H + t*4;
#pragma unroll
        for (int j=0;j<4;j++) wsplit(a[j], g_xh, g_xl, o+j);
    } else if (b < 7168){
        const float* src; bf16 *hi, *lo; int ld, kb, nb;
        if (b < 6144){ int q=b-4096; src=Wg0; ld=H2; hi=g_wgh; lo=g_wgl; kb=(q&31)*32; nb=(q>>5)*32; }
        else         { int q=b-6144; src=Wc0; ld=H;  hi=g_wch; lo=g_wcl; kb=(q&31)*32; nb=(q>>5)*32; }
        int tx = t&31, ty = t>>5;
#pragma unroll
        for (int i=0;i<32;i+=8) s[ty+i][tx] = src[(size_t)(kb+ty+i)*ld + nb+tx];
        __syncthreads();
#pragma unroll
        for (int i=0;i<32;i+=8)
            wsplit(s[tx][ty+i], hi, lo, (size_t)(nb+ty+i)*H + kb+tx);
    } else {
        int row = b - 7168;
        size_t o = (size_t)row*H + t*4;
        if (row < VOCAB){
            float4 v = ((const float4*)(emb + (size_t)row*H))[t];
            float a[4] = {v.x,v.y,v.z,v.w};
#pragma unroll
            for (int j=0;j<4;j++) wsplit(a[j], g_eh, g_el, o+j);
        } else {
#pragma unroll
            for (int j=0;j<4;j++){ g_eh[o+j]=__float2bfloat16(0.f); g_el[o+j]=__float2bfloat16(0.f); }
        }
    }
}

__global__ void outconv(const float* __restrict__ outT){
    int r = blockIdx.x, tid = threadIdx.x;
    int m = r>>7, t = r&127;
    float4 v = ((const float4*)(outT + ((size_t)t*BB + m)*H))[tid];
    float a[4] = {v.x,v.y,v.z,v.w};
    size_t o = (size_t)r*H + tid*4;
#pragma unroll
    for (int j=0;j<4;j++) wsplit(a[j], g_oh, g_ol, o+j);
}

// ---------------- HMMA bf16-split big GEMM (r13/r14, proven) ----------------
template<bool GRUL>
__global__ void __launch_bounds__(256, 2)
hgemm(const bf16* __restrict__ Ah, const bf16* __restrict__ Al,
      const bf16* __restrict__ Bh, const bf16* __restrict__ Bl,
      const float* __restrict__ bias, float* __restrict__ C, int N)
{
    extern __shared__ __align__(16) char smc[];
    const int tid = threadIdx.x, wid = tid>>5, lane = tid&31;
    const int n0 = blockIdx.x*64, m0 = blockIdx.y*128;
    const int wm = wid&3, wn = wid>>2;
    unsigned sb = (unsigned)__cvta_generic_to_shared(smc);

    auto stage = [&](int kc){
        char* base = smc + (kc&1)*HBUF;
#pragma unroll
        for (int u=0;u<8;u++){
            int e = tid + u*256;
            int pl = e>>10, i = e&1023, row = i>>3, g = i&7;
            const bf16* src = (pl?Al:Ah) + (size_t)(m0+row)*H + kc*64 + g*8;
            cp16(base + (pl?HA_L:0) + row*144 + g*16, src);
        }
#pragma unroll
        for (int u=0;u<4;u++){
            int e = tid + u*256;
            int pl = e>>9, i = e&511, row = i>>3, g = i&7;
            const bf16* src = (pl?Bl:Bh) + (size_t)(n0+row)*H + kc*64 + g*8;
            cp16(base + (pl?HB_L:HB_H) + row*144 + g*16, src);
        }
    };

    float cc[2][4][4];
#pragma unroll
    for (int a=0;a<2;a++)
#pragma unroll
        for (int b=0;b<4;b++)
#pragma unroll
            for (int q=0;q<4;q++) cc[a][b][q] = 0.f;

    stage(0); CP_COMMIT;
    for (int kc=0;kc<16;kc++){
        if (kc < 15){ stage(kc+1); CP_COMMIT; CP_WAIT1; } else CP_WAIT0;
        __syncthreads();
        unsigned bufb = sb + (kc&1)*HBUF;
        unsigned aB = bufb + (wm*32 + (lane&15))*144 + ((lane>>4)&1)*16;
        unsigned bB = bufb + HB_H + (wn*32 + (lane&7) + ((lane>>4)&1)*8)*144 + ((lane>>3)&1)*16;
#pragma unroll
        for (int ks=0;ks<4;ks++){
            unsigned ah[8], al[8], bh[8], bl[8];
            ldm4(ah[0],ah[1],ah[2],ah[3], aB + ks*32);
            ldm4(ah[4],ah[5],ah[6],ah[7], aB + 16*144 + ks*32);
            ldm4(al[0],al[1],al[2],al[3], aB + HA_L + ks*32);
            ldm4(al[4],al[5],al[6],al[7], aB + HA_L + 16*144 + ks*32);
            ldm4(bh[0],bh[1],bh[2],bh[3], bB + ks*32);
            ldm4(bh[4],bh[5],bh[6],bh[7], bB + 16*144 + ks*32);
            ldm4(bl[0],bl[1],bl[2],bl[3], bB + (HB_L-HB_H) + ks*32);
            ldm4(bl[4],bl[5],bl[6],bl[7], bB + (HB_L-HB_H) + 16*144 + ks*32);
#pragma unroll
            for (int fm=0;fm<2;fm++)
#pragma unroll
                for (int fn=0;fn<4;fn++){
                    mma16816(cc[fm][fn], ah+fm*4, bh+fn*2);
                    mma16816(cc[fm][fn], ah+fm*4, bl+fn*2);
                    mma16816(cc[fm][fn], al+fm*4, bh+fn*2);
                }
        }
        __syncthreads();
    }

    const int rb = lane>>2, cb = (lane&3)*2;
#pragma unroll
    for (int fm=0;fm<2;fm++){
#pragma unroll
        for (int half=0;half<2;half++){
            int r = m0 + wm*32 + fm*16 + rb + half*8;
            int r2 = GRUL ? ((r & 127)*BB + (r >> 7)) : r;
            float* crow = C + (size_t)r2*N;
#pragma unroll
            for (int fn=0;fn<4;fn++){
                int n = n0 + wn*32 + fn*8 + cb;
                if (n < N){
                    float2 v;
                    v.x = cc[fm][fn][half*2+0];
                    v.y = cc[fm][fn][half*2+1];
                    if (bias){
                        float2 b = *(const float2*)(bias + n);
                        v.x += b.x; v.y += b.y;
                    }
                    *(float2*)(crow + n) = v;
                }
            }
        }
    }
}

// ---------------- persistent HMMA recurrence: NB=64, wide CTAs ----------------
__global__ void __launch_bounds__(NTHR, 1)
rnn_persist(const float* __restrict__ bg0, const float* __restrict__ bc0,
            const float* __restrict__ bg1, const float* __restrict__ bc1)
{
    extern __shared__ __align__(16) char smc[];
    const int tid = threadIdx.x, c = blockIdx.x;
    const int lane = tid & 31, w = tid >> 5;
    unsigned sb = (unsigned)__cvta_generic_to_shared(smc);
    float* redf = (float*)(smc + SRED);

    for (int i = c*NTHR+tid; i < BB*H; i += NB*NTHR){
        bf16 z = __float2bfloat16(0.f);
        g_h0m[0][i]=0.f; g_h1m[i]=0.f;
        g_h0h[0][i]=z; g_h0l[0][i]=z; g_h1h[i]=z; g_h1l[i]=z;
    }
    gsync();

    // phase B warp roles: cg(4): 0,1=L0 col-groups, 2,3=L1; ksB(2): k64 halves
    const int cgB = w & 3, ksB = w >> 2;

    int cur = 0;
    for (int t = 0; t <= TT; t++){
        const bool do0 = (t < TT), do1 = (t > 0);
        const int nc = do1 ? 16 : 8;

        // ===================== PHASE A: gates (64 cols: 32 L0 + 32 L1) =====================
        {
            auto stage = [&](int kc){
                int bi = kc % 3;
                char* Ab = smc + SA + bi*BUFB;
                const bf16 *sh, *sl; int ko;
                if (kc < 8){ sh = g_h0h[cur]; sl = g_h0l[cur]; ko = kc*128; }
                else       { sh = g_h1h;      sl = g_h1l;      ko = (kc-8)*128; }
                #pragma unroll
                for (int u=0;u<4;u++){
                    int e = tid + u*NTHR; int pl = e>>9, i = e&511, row = i>>4, g = i&15;
                    cp16(Ab + pl*PLB + row*272 + g*16, (pl?sl:sh) + (size_t)row*H + ko + g*8);
                }
                char* Wb = smc + SW + bi*WBUF;
                #pragma unroll
                for (int u=0;u<4;u++){
                    int e = tid + u*NTHR; int pl = e>>9, i = e&511, r = i>>4, g = i&15;
                    size_t o1 = (size_t)(c*32 + r)*H2 + kc*128 + g*8;
                    cp16(Wb + pl*BUFB + (32+r)*272 + g*16, (pl?g_wgt1l:g_wgt1h) + o1);
                }
                if (kc < 8){
                    #pragma unroll
                    for (int u=0;u<4;u++){
                        int e = tid + u*NTHR; int pl = e>>9, i = e&511, r = i>>4, g = i&15;
                        size_t o0 = (size_t)(c*32 + r)*H + kc*128 + g*8;
                        cp16(Wb + pl*BUFB + r*272 + g*16, (pl?g_wgt0l:g_wgt0h) + o0);
                    }
                }
                CP_COMMIT;
            };
            stage(0); stage(1);
            float c0[2][4], c1[2][4], c2[2][4];
            #pragma unroll
            for (int fm=0;fm<2;fm++)
                #pragma unroll
                for (int q=0;q<4;q++){ c0[fm][q]=0.f; c1[fm][q]=0.f; c2[fm][q]=0.f; }

            for (int kc=0;kc<nc;kc++){
                if (kc+1 < nc) CP_WAIT1; else CP_WAIT0;
                __syncthreads();
                if (kc+2 < nc) stage(kc+2);
                const bool act = (w < 4) ? (do0 && kc < 8) : do1;
                if (act){
                    int bi = kc % 3;
                    unsigned sA = sb + SA + bi*BUFB;
                    unsigned sW = sb + SW + bi*WBUF;
                    unsigned wB = sW + (w*8 + (lane&7))*272 + ((lane>>3)&3)*16;
                    unsigned bh[16], bl[16];
                    ldm4(bh[0],bh[1],bh[2],bh[3],   wB);
                    ldm4(bh[4],bh[5],bh[6],bh[7],   wB + 64);
                    ldm4(bh[8],bh[9],bh[10],bh[11], wB + 128);
                    ldm4(bh[12],bh[13],bh[14],bh[15], wB + 192);
                    ldm4(bl[0],bl[1],bl[2],bl[3],   wB + BUFB);
                    ldm4(bl[4],bl[5],bl[6],bl[7],   wB + BUFB + 64);
                    ldm4(bl[8],bl[9],bl[10],bl[11], wB + BUFB + 128);
                    ldm4(bl[12],bl[13],bl[14],bl[15], wB + BUFB + 192);
                    unsigned aB = sA + (lane&15)*272 + ((lane>>4)&1)*16;
                    #pragma unroll
                    for (int s=0;s<8;s++){
                        unsigned a0[4], a1[4], l0[4], l1[4];
                        ldm4(a0[0],a0[1],a0[2],a0[3], aB + s*32);
                        ldm4(a1[0],a1[1],a1[2],a1[3], aB + 16*272 + s*32);
                        ldm4(l0[0],l0[1],l0[2],l0[3], aB + PLB + s*32);
                        ldm4(l1[0],l1[1],l1[2],l1[3], aB + PLB + 16*272 + s*32);
                        mma16816(c0[0], a0, bh+2*s); mma16816(c0[1], a1, bh+2*s);
                        mma16816(c1[0], a0, bl+2*s); mma16816(c1[1], a1, bl+2*s);
                        mma16816(c2[0], l0, bh+2*s); mma16816(c2[1], l1, bh+2*s);
                    }
                }
            }
            __syncthreads();
            #pragma unroll
            for (int fm=0;fm<2;fm++)
                #pragma unroll
                for (int q=0;q<4;q++){
                    int m = fm*16 + (lane>>2) + (q>>1)*8;
                    int nl = (lane&3)*2 + (q&1);
                    redf[(w*32 + m)*8 + nl] = c0[fm][q]+c1[fm][q]+c2[fm][q];
                }
            __syncthreads();
            #pragma unroll
            for (int u=0;u<8;u++){
                int o = tid + u*NTHR;
                int m = o>>6, col = o&63;
                int ng = col>>3, nl = col&7;
                float s = redf[(ng*32+m)*8+nl];
                if (col < 32){
                    if (do0){
                        int n = c*32 + col;
                        s += g_gx0[((size_t)t*BB+m)*H2 + n] + bg0[n];
                        float g = sigf(s);
                        if (n < H){
                            float v = g * g_h0m[cur][m*H+n];
                            wsplit(v, g_rh0h, g_rh0l, (size_t)m*H + n);
                        } else g_u0m[m*H + n-H] = g;
                    }
                } else {
                    if (do1){
                        int n = c*32 + col - 32;
                        s += bg1[n];
                        float g = sigf(s);
                        if (n < H){
                            float v = g * g_h1m[m*H+n];
                            wsplit(v, g_rh1h, g_rh1l, (size_t)m*H + n);
                        } else g_u1m[m*H + n-H] = g;
                    }
                }
            }
        }
        gsync();

        // ===================== PHASE B: candidates (32 cols: 16 L0 + 16 L1) =====================
        {
            auto stage = [&](int kc){
                int bi = kc % 3;
                char* A1b = smc + SA1 + bi*BUFB;
                const bf16 *sh, *sl; int ko;
                if (kc < 8){ sh = g_h0h[cur]; sl = g_h0l[cur]; ko = kc*128; }
                else       { sh = g_rh1h;     sl = g_rh1l;     ko = (kc-8)*128; }
                #pragma unroll
                for (int u=0;u<4;u++){
                    int e = tid + u*NTHR; int pl = e>>9, i = e&511, row = i>>4, g = i&15;
                    cp16(A1b + pl*PLB + row*272 + g*16, (pl?sl:sh) + (size_t)row*H + ko + g*8);
                }
                if (kc < 8){
                    char* A0b = smc + SA + bi*BUFB;
                    #pragma unroll
                    for (int u=0;u<4;u++){
                        int e = tid + u*NTHR; int pl = e>>9, i = e&511, row = i>>4, g = i&15;
                        cp16(A0b + pl*PLB + row*272 + g*16,
                             (pl?g_rh0l:g_rh0h) + (size_t)row*H + kc*128 + g*8);
                    }
                }
                char* Wb = smc + SW + bi*WBUF;
                #pragma unroll
                for (int u=0;u<2;u++){
                    int e = tid + u*NTHR; int pl = e>>8, i = e&255, r = i>>4, g = i&15;
                    size_t o1 = (size_t)(c*16 + r)*H2 + kc*128 + g*8;
                    cp16(Wb + pl*BUFB + (16+r)*272 + g*16, (pl?g_wct1l:g_wct1h) + o1);
                }
                if (kc < 8){
                    #pragma unroll
                    for (int u=0;u<2;u++){
                        int e = tid + u*NTHR; int pl = e>>8, i = e&255, r = i>>4, g = i&15;
                        size_t o0 = (size_t)(c*16 + r)*H + kc*128 + g*8;
                        cp16(Wb + pl*BUFB + r*272 + g*16, (pl?g_wct0l:g_wct0h) + o0);
                    }
                }
                CP_COMMIT;
            };
            stage(0); stage(1);
            float c0[2][4], c1[2][4], c2[2][4];
            #pragma unroll
            for (int fm=0;fm<2;fm++)
                #pragma unroll
                for (int q=0;q<4;q++){ c0[fm][q]=0.f; c1[fm][q]=0.f; c2[fm][q]=0.f; }

            for (int kc=0;kc<nc;kc++){
                if (kc+1 < nc) CP_WAIT1; else CP_WAIT0;
                __syncthreads();
                if (kc+2 < nc) stage(kc+2);
                const bool act = (cgB < 2) ? (do0 && kc < 8) : do1;
                if (act){
                    int bi = kc % 3;
                    unsigned sAx = sb + (cgB < 2 ? SA : SA1) + bi*BUFB;
                    unsigned sW = sb + SW + bi*WBUF;
                    int wrow = (cgB >= 2 ? 16 : 0) + (cgB&1)*8 + (lane&7);
                    unsigned wB = sW + wrow*272 + ((lane>>3)&3)*16 + ksB*128;
                    unsigned bh[8], bl[8];
                    ldm4(bh[0],bh[1],bh[2],bh[3], wB);
                    ldm4(bh[4],bh[5],bh[6],bh[7], wB + 64);
                    ldm4(bl[0],bl[1],bl[2],bl[3], wB + BUFB);
                    ldm4(bl[4],bl[5],bl[6],bl[7], wB + BUFB + 64);
                    unsigned aB = sAx + (lane&15)*272 + ((lane>>4)&1)*16 + ksB*128;
                    #pragma unroll
                    for (int s=0;s<4;s++){
                        unsigned a0[4], a1[4], l0[4], l1[4];
                        ldm4(a0[0],a0[1],a0[2],a0[3], aB + s*32);
                        ldm4(a1[0],a1[1],a1[2],a1[3], aB + 16*272 + s*32);
                        ldm4(l0[0],l0[1],l0[2],l0[3], aB + PLB + s*32);
                        ldm4(l1[0],l1[1],l1[2],l1[3], aB + PLB + 16*272 + s*32);
                        mma16816(c0[0], a0, bh+2*s); mma16816(c0[1], a1, bh+2*s);
                        mma16816(c1[0], a0, bl+2*s); mma16816(c1[1], a1, bl+2*s);
                        mma16816(c2[0], l0, bh+2*s); mma16816(c2[1], l1, bh+2*s);
                    }
                }
            }
            __syncthreads();
            #pragma unroll
            for (int fm=0;fm<2;fm++)
                #pragma unroll
                for (int q=0;q<4;q++){
                    int m = fm*16 + (lane>>2) + (q>>1)*8;
                    int nl = (lane&3)*2 + (q&1);
                    redf[((ksB*4+cgB)*32 + m)*8 + nl] = c0[fm][q]+c1[fm][q]+c2[fm][q];
                }
            __syncthreads();
            #pragma unroll
            for (int u=0;u<4;u++){
                int o = tid + u*NTHR;
                int m = o>>5, col = o&31;
                int cg2 = col>>3, nl = col&7;
                float s = redf[((0*4+cg2)*32+m)*8+nl] + redf[((1*4+cg2)*32+m)*8+nl];
                if (col < 16){
                    if (do0){
                        int n = c*16 + col;
                        s += g_cx0[((size_t)t*BB+m)*H + n] + bc0[n];
                        float cc = tanhx(s);
                        float uu = g_u0m[m*H+n];
                        float hn = uu * g_h0m[cur][m*H+n] + (1.f-uu)*cc;
                        g_h0m[cur^1][m*H+n] = hn;
                        wsplit(hn, g_h0h[cur^1], g_h0l[cur^1], (size_t)m*H + n);
                    }
                } else {
                    if (do1){
                        int n = c*16 + col - 16;
                        s += bc1[n];
                        float cc = tanhx(s);
                        float uu = g_u1m[m*H+n];
                        float hn = uu * g_h1m[m*H+n] + (1.f-uu)*cc;
                        g_h1m[m*H+n] = hn;
                        wsplit(hn, g_h1h, g_h1l, (size_t)m*H + n);
                        g_outT[((size_t)(t-1)*BB+m)*H + n] = hn;
                    }
                }
            }
        }
        cur ^= 1;
        gsync();
    }
}

// ---------------- launch ----------------
extern "C" void kernel_launch(void* const* d_in, const int* in_sizes, int n_in,
                              void* d_out, int out_size)
{
    const int*   idx = (const int*)  d_in[0];
    const float* emb = (const float*)d_in[1];
    const float* Wg0 = (const float*)d_in[2];
    const float* bg0 = (const float*)d_in[3];
    const float* Wc0 = (const float*)d_in[4];
    const float* bc0 = (const float*)d_in[5];
    const float* Wg1 = (const float*)d_in[6];
    const float* bg1 = (const float*)d_in[7];
    const float* Wc1 = (const float*)d_in[8];
    const float* bc1 = (const float*)d_in[9];
    const float* smb = (const float*)d_in[10];
    float* out = (float*)d_out;

    float *pgx0,*pcx0,*poutT;
    bf16 *pxh,*pxl,*poh,*pol,*pwgh,*pwgl,*pwch,*pwcl,*peh,*pel;
    cudaGetSymbolAddress((void**)&pgx0,  g_gx0);
    cudaGetSymbolAddress((void**)&pcx0,  g_cx0);
    cudaGetSymbolAddress((void**)&poutT, g_outT);
    cudaGetSymbolAddress((void**)&pxh,   g_xh);
    cudaGetSymbolAddress((void**)&pxl,   g_xl);
    cudaGetSymbolAddress((void**)&poh,   g_oh);
    cudaGetSymbolAddress((void**)&pol,   g_ol);
    cudaGetSymbolAddress((void**)&pwgh,  g_wgh);
    cudaGetSymbolAddress((void**)&pwgl,  g_wgl);
    cudaGetSymbolAddress((void**)&pwch,  g_wch);
    cudaGetSymbolAddress((void**)&pwcl,  g_wcl);
    cudaGetSymbolAddress((void**)&peh,   g_eh);
    cudaGetSymbolAddress((void**)&pel,   g_el);

    static bool attr_set = false;
    if (!attr_set){
        cudaFuncSetAttribute(rnn_persist, cudaFuncAttributeMaxDynamicSharedMemorySize, RSM);
        cudaFuncSetAttribute(hgemm<true>,  cudaFuncAttributeMaxDynamicSharedMemorySize, HSM);
        cudaFuncSetAttribute(hgemm<false>, cudaFuncAttributeMaxDynamicSharedMemorySize, HSM);
        attr_set = true;
    }

    prep_wq<<<9216, 256>>>(Wg0, Wg1, Wc0, Wc1);
    prep_cv<<<7168 + VPAD, 256>>>(idx, emb, Wg0, Wc0);

    hgemm<true><<<dim3(H2/64, MROWS/128), 256, HSM>>>(pxh, pxl, pwgh, pwgl, nullptr, pgx0, H2);
    hgemm<true><<<dim3(H/64,  MROWS/128), 256, HSM>>>(pxh, pxl, pwch, pwcl, nullptr, pcx0, H);

    rnn_persist<<<NB, NTHR, RSM>>>(bg0, bc0, bg1, bc1);

    outconv<<<MROWS, 256>>>(poutT);
    hgemm<false><<<dim3(VPAD/64, MROWS/128), 256, HSM>>>(poh, pol, peh, pel, smb, out, VOCAB);
}

// round 16
// speedup vs baseline: 1.3980x; 1.3980x over previous
#include <cuda_runtime.h>
#include <cuda_bf16.h>
#include <math.h>
typedef unsigned long long ull;
typedef __nv_bfloat16 bf16;

#define VOCAB 10000
#define VPAD  10048
#define H 1024
#define H2 2048
#define BB 32
#define TT 128
#define MROWS (BB*TT)
#define NB 128
#define NTHR 512

// rnn smem (bytes): chunk=256 bf16; plane = 32 rows x 528B = 16896; buf(hi+lo)=33792
#define PLB  16896
#define BUFB 33792
#define SA   0
#define SA1  67584
#define SW   135168
#define SRED 202752
#define RSM  219136

// hgemm smem (bytes)
#define HA_L 18432
#define HB_H 36864
#define HB_L 46080
#define HBUF 55296
#define HSM  (2*HBUF)

// ---------------- device scratch ----------------
__device__ __align__(16) float g_gx0[(size_t)TT*BB*H2];   // [t][m][n]
__device__ __align__(16) float g_cx0[(size_t)TT*BB*H];
__device__ __align__(16) float g_outT[(size_t)TT*BB*H];
__device__ __align__(16) float g_h0m[2][BB*H];
__device__ __align__(16) float g_h1m[BB*H];
__device__ __align__(16) float g_u0m[BB*H];
__device__ __align__(16) float g_u1m[BB*H];
__device__ __align__(16) bf16 g_h0h[2][BB*H], g_h0l[2][BB*H];
__device__ __align__(16) bf16 g_h1h[BB*H],  g_h1l[BB*H];
__device__ __align__(16) bf16 g_rh0h[BB*H], g_rh0l[BB*H];
__device__ __align__(16) bf16 g_rh1h[BB*H], g_rh1l[BB*H];
__device__ __align__(16) bf16 g_wgt0h[(size_t)H2*H],  g_wgt0l[(size_t)H2*H];
__device__ __align__(16) bf16 g_wgt1h[(size_t)H2*H2], g_wgt1l[(size_t)H2*H2];
__device__ __align__(16) bf16 g_wct0h[(size_t)H*H],   g_wct0l[(size_t)H*H];
__device__ __align__(16) bf16 g_wct1h[(size_t)H*H2],  g_wct1l[(size_t)H*H2];
__device__ __align__(16) bf16 g_xh[(size_t)MROWS*H], g_xl[(size_t)MROWS*H];
__device__ __align__(16) bf16 g_oh[(size_t)MROWS*H], g_ol[(size_t)MROWS*H];
__device__ __align__(16) bf16 g_wgh[(size_t)H2*H],  g_wgl[(size_t)H2*H];
__device__ __align__(16) bf16 g_wch[(size_t)H*H],   g_wcl[(size_t)H*H];
__device__ __align__(16) bf16 g_eh[(size_t)VPAD*H], g_el[(size_t)VPAD*H];
__device__ volatile unsigned g_cnt;
__device__ volatile unsigned g_gen;

// ---------------- helpers ----------------
__device__ __forceinline__ float sigf(float x){ return __fdividef(1.f, 1.f+__expf(-x)); }
__device__ __forceinline__ float tanhx(float x){ return 1.f-__fdividef(2.f, __expf(2.f*x)+1.f); }

__device__ __forceinline__ void cp16(void* d, const void* s){
    unsigned ds = (unsigned)__cvta_generic_to_shared(d);
    asm volatile("cp.async.cg.shared.global [%0], [%1], 16;" :: "r"(ds), "l"(s) : "memory");
}
#define CP_COMMIT asm volatile("cp.async.commit_group;" ::: "memory")
#define CP_WAIT0  asm volatile("cp.async.wait_group 0;" ::: "memory")
#define CP_WAIT1  asm volatile("cp.async.wait_group 1;" ::: "memory")

__device__ __forceinline__ void gsync(){
    __threadfence();
    __syncthreads();
    if (threadIdx.x == 0){
        unsigned gen = g_gen;
        unsigned old = atomicAdd((unsigned*)&g_cnt, 1u);
        if (old == NB-1){ g_cnt = 0; __threadfence(); g_gen = gen+1; }
        else { while (g_gen == gen) { __nanosleep(40); } }
    }
    __syncthreads();
}

__device__ __forceinline__ void ldm4(unsigned& r0, unsigned& r1, unsigned& r2, unsigned& r3,
                                     unsigned addr){
    asm volatile("ldmatrix.sync.aligned.m8n8.x4.shared.b16 {%0,%1,%2,%3}, [%4];"
        : "=r"(r0), "=r"(r1), "=r"(r2), "=r"(r3) : "r"(addr));
}
__device__ __forceinline__ void mma16816(float* c, const unsigned* a, const unsigned* b){
    asm volatile("mma.sync.aligned.m16n8k16.row.col.f32.bf16.bf16.f32 "
        "{%0,%1,%2,%3},{%4,%5,%6,%7},{%8,%9},{%0,%1,%2,%3};"
        : "+f"(c[0]), "+f"(c[1]), "+f"(c[2]), "+f"(c[3])
        : "r"(a[0]), "r"(a[1]), "r"(a[2]), "r"(a[3]), "r"(b[0]), "r"(b[1]));
}
__device__ __forceinline__ void wsplit(float v, bf16* hp, bf16* lp, size_t o){
    bf16 h = __float2bfloat16(v);
    hp[o] = h; lp[o] = __float2bfloat16(v - __bfloat162float(h));
}

// ---------------- prep kernels ----------------
__global__ void prep_wq(const float* __restrict__ Wg0, const float* __restrict__ Wg1,
                        const float* __restrict__ Wc0, const float* __restrict__ Wc1){
    __shared__ float s[32][33];
    int b = blockIdx.x;
    const float* src; bf16 *dh, *dl; int srow0, ld, ldd, bx, by;
    if (b < 2048){      src=Wg0; srow0=1024; ld=H2; dh=g_wgt0h; dl=g_wgt0l; ldd=H;  bx=b&31; by=b>>5; }
    else if (b<6144){ int q=b-2048; src=Wg1; srow0=0; ld=H2; dh=g_wgt1h; dl=g_wgt1l; ldd=H2; bx=q&63; by=q>>6; }
    else if (b<7168){ int q=b-6144; src=Wc0; srow0=1024; ld=H; dh=g_wct0h; dl=g_wct0l; ldd=H; bx=q&31; by=q>>5; }
    else {            int q=b-7168; src=Wc1; srow0=0; ld=H; dh=g_wct1h; dl=g_wct1l; ldd=H2; bx=q&63; by=q>>6; }
    int kb = bx*32, nb = by*32;
    int t = threadIdx.x, tx = t&31, ty = t>>5;
#pragma unroll
    for (int i=0;i<32;i+=8) s[ty+i][tx] = src[(size_t)(srow0+kb+ty+i)*ld + nb+tx];
    __syncthreads();
#pragma unroll
    for (int i=0;i<32;i+=8)
        wsplit(s[tx][ty+i], dh, dl, (size_t)(nb+ty+i)*ldd + kb+tx);
}

__global__ void prep_cv(const int* __restrict__ idx, const float* __restrict__ emb,
                        const float* __restrict__ Wg0, const float* __restrict__ Wc0){
    __shared__ float s[32][33];
    int b = blockIdx.x, t = threadIdx.x;
    if (b < 4096){
        float4 v = ((const float4*)(emb + (size_t)idx[b]*H))[t];
        float a[4] = {v.x,v.y,v.z,v.w};
        size_t o = (size_t)b*H + t*4;
#pragma unroll
        for (int j=0;j<4;j++) wsplit(a[j], g_xh, g_xl, o+j);
    } else if (b < 7168){
        const float* src; bf16 *hi, *lo; int ld, kb, nb;
        if (b < 6144){ int q=b-4096; src=Wg0; ld=H2; hi=g_wgh; lo=g_wgl; kb=(q&31)*32; nb=(q>>5)*32; }
        else         { int q=b-6144; src=Wc0; ld=H;  hi=g_wch; lo=g_wcl; kb=(q&31)*32; nb=(q>>5)*32; }
        int tx = t&31, ty = t>>5;
#pragma unroll
        for (int i=0;i<32;i+=8) s[ty+i][tx] = src[(size_t)(kb+ty+i)*ld + nb+tx];
        __syncthreads();
#pragma unroll
        for (int i=0;i<32;i+=8)
            wsplit(s[tx][ty+i], hi, lo, (size_t)(nb+ty+i)*H + kb+tx);
    } else {
        int row = b - 7168;
        size_t o = (size_t)row*H + t*4;
        if (row < VOCAB){
            float4 v = ((const float4*)(emb + (size_t)row*H))[t];
            float a[4] = {v.x,v.y,v.z,v.w};
#pragma unroll
            for (int j=0;j<4;j++) wsplit(a[j], g_eh, g_el, o+j);
        } else {
#pragma unroll
            for (int j=0;j<4;j++){ g_eh[o+j]=__float2bfloat16(0.f); g_el[o+j]=__float2bfloat16(0.f); }
        }
    }
}

__global__ void outconv(const float* __restrict__ outT){
    int r = blockIdx.x, tid = threadIdx.x;
    int m = r>>7, t = r&127;
    float4 v = ((const float4*)(outT + ((size_t)t*BB + m)*H))[tid];
    float a[4] = {v.x,v.y,v.z,v.w};
    size_t o = (size_t)r*H + tid*4;
#pragma unroll
    for (int j=0;j<4;j++) wsplit(a[j], g_oh, g_ol, o+j);
}

// ---------------- HMMA bf16-split big GEMM (r13/r14, proven) ----------------
template<bool GRUL>
__global__ void __launch_bounds__(256, 2)
hgemm(const bf16* __restrict__ Ah, const bf16* __restrict__ Al,
      const bf16* __restrict__ Bh, const bf16* __restrict__ Bl,
      const float* __restrict__ bias, float* __restrict__ C, int N)
{
    extern __shared__ __align__(16) char smc[];
    const int tid = threadIdx.x, wid = tid>>5, lane = tid&31;
    const int n0 = blockIdx.x*64, m0 = blockIdx.y*128;
    const int wm = wid&3, wn = wid>>2;
    unsigned sb = (unsigned)__cvta_generic_to_shared(smc);

    auto stage = [&](int kc){
        char* base = smc + (kc&1)*HBUF;
#pragma unroll
        for (int u=0;u<8;u++){
            int e = tid + u*256;
            int pl = e>>10, i = e&1023, row = i>>3, g = i&7;
            const bf16* src = (pl?Al:Ah) + (size_t)(m0+row)*H + kc*64 + g*8;
            cp16(base + (pl?HA_L:0) + row*144 + g*16, src);
        }
#pragma unroll
        for (int u=0;u<4;u++){
            int e = tid + u*256;
            int pl = e>>9, i = e&511, row = i>>3, g = i&7;
            const bf16* src = (pl?Bl:Bh) + (size_t)(n0+row)*H + kc*64 + g*8;
            cp16(base + (pl?HB_L:HB_H) + row*144 + g*16, src);
        }
    };

    float cc[2][4][4];
#pragma unroll
    for (int a=0;a<2;a++)
#pragma unroll
        for (int b=0;b<4;b++)
#pragma unroll
            for (int q=0;q<4;q++) cc[a][b][q] = 0.f;

    stage(0); CP_COMMIT;
    for (int kc=0;kc<16;kc++){
        if (kc < 15){ stage(kc+1); CP_COMMIT; CP_WAIT1; } else CP_WAIT0;
        __syncthreads();
        unsigned bufb = sb + (kc&1)*HBUF;
        unsigned aB = bufb + (wm*32 + (lane&15))*144 + ((lane>>4)&1)*16;
        unsigned bB = bufb + HB_H + (wn*32 + (lane&7) + ((lane>>4)&1)*8)*144 + ((lane>>3)&1)*16;
#pragma unroll
        for (int ks=0;ks<4;ks++){
            unsigned ah[8], al[8], bh[8], bl[8];
            ldm4(ah[0],ah[1],ah[2],ah[3], aB + ks*32);
            ldm4(ah[4],ah[5],ah[6],ah[7], aB + 16*144 + ks*32);
            ldm4(al[0],al[1],al[2],al[3], aB + HA_L + ks*32);
            ldm4(al[4],al[5],al[6],al[7], aB + HA_L + 16*144 + ks*32);
            ldm4(bh[0],bh[1],bh[2],bh[3], bB + ks*32);
            ldm4(bh[4],bh[5],bh[6],bh[7], bB + 16*144 + ks*32);
            ldm4(bl[0],bl[1],bl[2],bl[3], bB + (HB_L-HB_H) + ks*32);
            ldm4(bl[4],bl[5],bl[6],bl[7], bB + (HB_L-HB_H) + 16*144 + ks*32);
#pragma unroll
            for (int fm=0;fm<2;fm++)
#pragma unroll
                for (int fn=0;fn<4;fn++){
                    mma16816(cc[fm][fn], ah+fm*4, bh+fn*2);
                    mma16816(cc[fm][fn], ah+fm*4, bl+fn*2);
                    mma16816(cc[fm][fn], al+fm*4, bh+fn*2);
                }
        }
        __syncthreads();
    }

    const int rb = lane>>2, cb = (lane&3)*2;
#pragma unroll
    for (int fm=0;fm<2;fm++){
#pragma unroll
        for (int half=0;half<2;half++){
            int r = m0 + wm*32 + fm*16 + rb + half*8;
            int r2 = GRUL ? ((r & 127)*BB + (r >> 7)) : r;
            float* crow = C + (size_t)r2*N;
#pragma unroll
            for (int fn=0;fn<4;fn++){
                int n = n0 + wn*32 + fn*8 + cb;
                if (n < N){
                    float2 v;
                    v.x = cc[fm][fn][half*2+0];
                    v.y = cc[fm][fn][half*2+1];
                    if (bias){
                        float2 b = *(const float2*)(bias + n);
                        v.x += b.x; v.y += b.y;
                    }
                    *(float2*)(crow + n) = v;
                }
            }
        }
    }
}

// ---------------- persistent HMMA recurrence (chunk=256, ring-2, 512 thr) ----------------
__global__ void __launch_bounds__(NTHR, 1)
rnn_persist(const float* __restrict__ bg0, const float* __restrict__ bc0,
            const float* __restrict__ bg1, const float* __restrict__ bc1)
{
    extern __shared__ __align__(16) char smc[];
    const int tid = threadIdx.x, c = blockIdx.x;
    const int lane = tid & 31, w = tid >> 5;
    unsigned sb = (unsigned)__cvta_generic_to_shared(smc);
    float* redf = (float*)(smc + SRED);

    for (int i = c*NTHR+tid; i < BB*H; i += NB*NTHR){
        bf16 z = __float2bfloat16(0.f);
        g_h0m[0][i]=0.f; g_h1m[i]=0.f;
        g_h0h[0][i]=z; g_h0l[0][i]=z; g_h1h[i]=z; g_h1l[i]=z;
    }
    gsync();

    const int ngA = w & 3, ksA = w >> 2;   // 4 n-groups x 4 k-split (64 k each)
    const int lB = w & 1, ksB = w >> 1;    // 2 layers x 8 k-split (32 k each)

    int cur = 0;
    for (int t = 0; t <= TT; t++){
        const bool do0 = (t < TT), do1 = (t > 0);
        const int nc = do1 ? 8 : 4;

        // ===================== PHASE A: gates =====================
        {
            auto stage = [&](int kc){
                int bi = kc & 1;
                char* Ab = smc + SA + bi*BUFB;
                const bf16 *sh, *sl; int ko;
                if (kc < 4){ sh = g_h0h[cur]; sl = g_h0l[cur]; ko = kc*256; }
                else       { sh = g_h1h;      sl = g_h1l;      ko = (kc-4)*256; }
                #pragma unroll
                for (int u=0;u<4;u++){
                    int e = tid + u*NTHR; int pl = e>>10, i = e&1023, row = i>>5, g = i&31;
                    cp16(Ab + pl*PLB + row*528 + g*16, (pl?sl:sh) + (size_t)row*H + ko + g*8);
                }
                char* Wb = smc + SW + bi*BUFB;
                #pragma unroll
                for (int u=0;u<2;u++){
                    int e = tid + u*NTHR; int pl = e>>9, i = e&511, r = i>>5, g = i&31;
                    size_t o1 = (size_t)(c*16 + r)*H2 + kc*256 + g*8;
                    cp16(Wb + pl*PLB + (16+r)*528 + g*16, (pl?g_wgt1l:g_wgt1h) + o1);
                }
                if (kc < 4){
                    #pragma unroll
                    for (int u=0;u<2;u++){
                        int e = tid + u*NTHR; int pl = e>>9, i = e&511, r = i>>5, g = i&31;
                        size_t o0 = (size_t)(c*16 + r)*H + kc*256 + g*8;
                        cp16(Wb + pl*PLB + r*528 + g*16, (pl?g_wgt0l:g_wgt0h) + o0);
                    }
                }
                CP_COMMIT;
            };
            stage(0);
            float c0[2][4], c1[2][4], c2[2][4];
            #pragma unroll
            for (int fm=0;fm<2;fm++)
                #pragma unroll
                for (int q=0;q<4;q++){ c0[fm][q]=0.f; c1[fm][q]=0.f; c2[fm][q]=0.f; }

            for (int kc=0;kc<nc;kc++){
                CP_WAIT0;
                __syncthreads();
                if (kc+1 < nc) stage(kc+1);
                const bool act = (ngA < 2) ? (do0 && kc < 4) : do1;
                if (act){
                    int bi = kc & 1;
                    unsigned sA = sb + SA + bi*BUFB;
                    unsigned sW = sb + SW + bi*BUFB;
                    unsigned wB = sW + (ngA*8 + (lane&7))*528 + ((lane>>3)&3)*16 + ksA*128;
                    unsigned bh[8], bl[8];
                    ldm4(bh[0],bh[1],bh[2],bh[3], wB);
                    ldm4(bh[4],bh[5],bh[6],bh[7], wB + 64);
                    ldm4(bl[0],bl[1],bl[2],bl[3], wB + PLB);
                    ldm4(bl[4],bl[5],bl[6],bl[7], wB + PLB + 64);
                    unsigned aB = sA + (lane&15)*528 + ((lane>>4)&1)*16 + ksA*128;
                    #pragma unroll
                    for (int s=0;s<4;s++){
                        unsigned a0[4], a1[4], l0[4], l1[4];
                        ldm4(a0[0],a0[1],a0[2],a0[3], aB + s*32);
                        ldm4(a1[0],a1[1],a1[2],a1[3], aB + 16*528 + s*32);
                        ldm4(l0[0],l0[1],l0[2],l0[3], aB + PLB + s*32);
                        ldm4(l1[0],l1[1],l1[2],l1[3], aB + PLB + 16*528 + s*32);
                        mma16816(c0[0], a0, bh+2*s); mma16816(c0[1], a1, bh+2*s);
                        mma16816(c1[0], a0, bl+2*s); mma16816(c1[1], a1, bl+2*s);
                        mma16816(c2[0], l0, bh+2*s); mma16816(c2[1], l1, bh+2*s);
                    }
                }
            }
            __syncthreads();
            #pragma unroll
            for (int fm=0;fm<2;fm++)
                #pragma unroll
                for (int q=0;q<4;q++){
                    int m = fm*16 + (lane>>2) + (q>>1)*8;
                    int nl = (lane&3)*2 + (q&1);
                    redf[((ksA*4+ngA)*32 + m)*8 + nl] = c0[fm][q]+c1[fm][q]+c2[fm][q];
                }
            __syncthreads();
            #pragma unroll
            for (int u=0;u<2;u++){
                int o = tid + u*NTHR;
                int m = o>>5, col = o&31;
                int ng2 = col>>3, nl = col&7;
                float s = redf[((0*4+ng2)*32+m)*8+nl] + redf[((1*4+ng2)*32+m)*8+nl]
                        + redf[((2*4+ng2)*32+m)*8+nl] + redf[((3*4+ng2)*32+m)*8+nl];
                if (col < 16){
                    if (do0){
                        int n = c*16 + col;
                        s += g_gx0[((size_t)t*BB+m)*H2 + n] + bg0[n];
                        float g = sigf(s);
                        if (n < H){
                            float v = g * g_h0m[cur][m*H+n];
                            wsplit(v, g_rh0h, g_rh0l, (size_t)m*H + n);
                        } else g_u0m[m*H + n-H] = g;
                    }
                } else {
                    if (do1){
                        int n = c*16 + col - 16;
                        s += bg1[n];
                        float g = sigf(s);
                        if (n < H){
                            float v = g * g_h1m[m*H+n];
                            wsplit(v, g_rh1h, g_rh1l, (size_t)m*H + n);
                        } else g_u1m[m*H + n-H] = g;
                    }
                }
            }
        }
        gsync();

        // ===================== PHASE B: candidates + update =====================
        {
            auto stage = [&](int kc){
                int bi = kc & 1;
                char* A1b = smc + SA1 + bi*BUFB;
                const bf16 *sh, *sl; int ko;
                if (kc < 4){ sh = g_h0h[cur]; sl = g_h0l[cur]; ko = kc*256; }
                else       { sh = g_rh1h;     sl = g_rh1l;     ko = (kc-4)*256; }
                #pragma unroll
                for (int u=0;u<4;u++){
                    int e = tid + u*NTHR; int pl = e>>10, i = e&1023, row = i>>5, g = i&31;
                    cp16(A1b + pl*PLB + row*528 + g*16, (pl?sl:sh) + (size_t)row*H + ko + g*8);
                }
                if (kc < 4){
                    char* A0b = smc + SA + bi*BUFB;
                    #pragma unroll
                    for (int u=0;u<4;u++){
                        int e = tid + u*NTHR; int pl = e>>10, i = e&1023, row = i>>5, g = i&31;
                        cp16(A0b + pl*PLB + row*528 + g*16,
                             (pl?g_rh0l:g_rh0h) + (size_t)row*H + kc*256 + g*8);
                    }
                }
                char* Wb = smc + SW + bi*BUFB;
                {
                    int e = tid; int pl = e>>8, i = e&255, r = i>>5, g = i&31;
                    size_t o1 = (size_t)(c*8 + r)*H2 + kc*256 + g*8;
                    cp16(Wb + pl*PLB + (8+r)*528 + g*16, (pl?g_wct1l:g_wct1h) + o1);
                }
                if (kc < 4){
                    int e = tid; int pl = e>>8, i = e&255, r = i>>5, g = i&31;
                    size_t o0 = (size_t)(c*8 + r)*H + kc*256 + g*8;
                    cp16(Wb + pl*PLB + r*528 + g*16, (pl?g_wct0l:g_wct0h) + o0);
                }
                CP_COMMIT;
            };
            stage(0);
            float c0[2][4], c1[2][4], c2[2][4];
            #pragma unroll
            for (int fm=0;fm<2;fm++)
                #pragma unroll
                for (int q=0;q<4;q++){ c0[fm][q]=0.f; c1[fm][q]=0.f; c2[fm][q]=0.f; }

            for (int kc=0;kc<nc;kc++){
                CP_WAIT0;
                __syncthreads();
                if (kc+1 < nc) stage(kc+1);
                const bool act = (lB == 0) ? (do0 && kc < 4) : do1;
                if (act){
                    int bi = kc & 1;
                    unsigned sAx = sb + (lB ? SA1 : SA) + bi*BUFB;
                    unsigned sW = sb + SW + bi*BUFB;
                    unsigned wB = sW + (lB*8 + (lane&7))*528 + ((lane>>3)&3)*16 + ksB*64;
                    unsigned bh[4], bl[4];
                    ldm4(bh[0],bh[1],bh[2],bh[3], wB);
                    ldm4(bl[0],bl[1],bl[2],bl[3], wB + PLB);
                    unsigned aB = sAx + (lane&15)*528 + ((lane>>4)&1)*16 + ksB*64;
                    #pragma unroll
                    for (int s=0;s<2;s++){
                        unsigned a0[4], a1[4], l0[4], l1[4];
                        ldm4(a0[0],a0[1],a0[2],a0[3], aB + s*32);
                        ldm4(a1[0],a1[1],a1[2],a1[3], aB + 16*528 + s*32);
                        ldm4(l0[0],l0[1],l0[2],l0[3], aB + PLB + s*32);
                        ldm4(l1[0],l1[1],l1[2],l1[3], aB + PLB + 16*528 + s*32);
                        mma16816(c0[0], a0, bh+2*s); mma16816(c0[1], a1, bh+2*s);
                        mma16816(c1[0], a0, bl+2*s); mma16816(c1[1], a1, bl+2*s);
                        mma16816(c2[0], l0, bh+2*s); mma16816(c2[1], l1, bh+2*s);
                    }
                }
            }
            __syncthreads();
            #pragma unroll
            for (int fm=0;fm<2;fm++)
                #pragma unroll
                for (int q=0;q<4;q++){
                    int m = fm*16 + (lane>>2) + (q>>1)*8;
                    int nl = (lane&3)*2 + (q&1);
                    redf[((ksB*2+lB)*32 + m)*8 + nl] = c0[fm][q]+c1[fm][q]+c2[fm][q];
                }
            __syncthreads();
            {
                int o = tid;
                int m = o>>4, col = o&15;
                int lg = col>>3, nl = col&7;
                float s = 0.f;
                #pragma unroll
                for (int ks=0;ks<8;ks++)
                    s += redf[((ks*2+lg)*32+m)*8+nl];
                if (lg == 0){
                    if (do0){
                        int n = c*8 + nl;
                        s += g_cx0[((size_t)t*BB+m)*H + n] + bc0[n];
                        float cc = tanhx(s);
                        float uu = g_u0m[m*H+n];
                        float hn = uu * g_h0m[cur][m*H+n] + (1.f-uu)*cc;
                        g_h0m[cur^1][m*H+n] = hn;
                        wsplit(hn, g_h0h[cur^1], g_h0l[cur^1], (size_t)m*H + n);
                    }
                } else {
                    if (do1){
                        int n = c*8 + nl;
                        s += bc1[n];
                        float cc = tanhx(s);
                        float uu = g_u1m[m*H+n];
                        float hn = uu * g_h1m[m*H+n] + (1.f-uu)*cc;
                        g_h1m[m*H+n] = hn;
                        wsplit(hn, g_h1h, g_h1l, (size_t)m*H + n);
                        g_outT[((size_t)(t-1)*BB+m)*H + n] = hn;
                    }
                }
            }
        }
        cur ^= 1;
        gsync();
    }
}

// ---------------- launch ----------------
extern "C" void kernel_launch(void* const* d_in, const int* in_sizes, int n_in,
                              void* d_out, int out_size)
{
    const int*   idx = (const int*)  d_in[0];
    const float* emb = (const float*)d_in[1];
    const float* Wg0 = (const float*)d_in[2];
    const float* bg0 = (const float*)d_in[3];
    const float* Wc0 = (const float*)d_in[4];
    const float* bc0 = (const float*)d_in[5];
    const float* Wg1 = (const float*)d_in[6];
    const float* bg1 = (const float*)d_in[7];
    const float* Wc1 = (const float*)d_in[8];
    const float* bc1 = (const float*)d_in[9];
    const float* smb = (const float*)d_in[10];
    float* out = (float*)d_out;

    float *pgx0,*pcx0,*poutT;
    bf16 *pxh,*pxl,*poh,*pol,*pwgh,*pwgl,*pwch,*pwcl,*peh,*pel;
    cudaGetSymbolAddress((void**)&pgx0,  g_gx0);
    cudaGetSymbolAddress((void**)&pcx0,  g_cx0);
    cudaGetSymbolAddress((void**)&poutT, g_outT);
    cudaGetSymbolAddress((void**)&pxh,   g_xh);
    cudaGetSymbolAddress((void**)&pxl,   g_xl);
    cudaGetSymbolAddress((void**)&poh,   g_oh);
    cudaGetSymbolAddress((void**)&pol,   g_ol);
    cudaGetSymbolAddress((void**)&pwgh,  g_wgh);
    cudaGetSymbolAddress((void**)&pwgl,  g_wgl);
    cudaGetSymbolAddress((void**)&pwch,  g_wch);
    cudaGetSymbolAddress((void**)&pwcl,  g_wcl);
    cudaGetSymbolAddress((void**)&peh,   g_eh);
    cudaGetSymbolAddress((void**)&pel,   g_el);

    static bool attr_set = false;
    if (!attr_set){
        cudaFuncSetAttribute(rnn_persist, cudaFuncAttributeMaxDynamicSharedMemorySize, RSM);
        cudaFuncSetAttribute(hgemm<true>,  cudaFuncAttributeMaxDynamicSharedMemorySize, HSM);
        cudaFuncSetAttribute(hgemm<false>, cudaFuncAttributeMaxDynamicSharedMemorySize, HSM);
        attr_set = true;
    }

    prep_wq<<<9216, 256>>>(Wg0, Wg1, Wc0, Wc1);
    prep_cv<<<7168 + VPAD, 256>>>(idx, emb, Wg0, Wc0);

    hgemm<true><<<dim3(H2/64, MROWS/128), 256, HSM>>>(pxh, pxl, pwgh, pwgl, nullptr, pgx0, H2);
    hgemm<true><<<dim3(H/64,  MROWS/128), 256, HSM>>>(pxh, pxl, pwch, pwcl, nullptr, pcx0, H);

    rnn_persist<<<NB, NTHR, RSM>>>(bg0, bc0, bg1, bc1);

    outconv<<<MROWS, 256>>>(poutT);
    hgemm<false><<<dim3(VPAD/64, MROWS/128), 256, HSM>>>(poh, pol, peh, pel, smb, out, VOCAB);
}

// round 17
// speedup vs baseline: 1.4109x; 1.0092x over previous
#include <cuda_runtime.h>
#include <cuda_bf16.h>
#include <math.h>
typedef unsigned long long ull;
typedef __nv_bfloat16 bf16;

#define VOCAB 10000
#define VPAD  10048
#define H 1024
#define H2 2048
#define BB 32
#define TT 128
#define MROWS (BB*TT)
#define NB 128
#define NTHR 512

// rnn smem (bytes): chunk=128; plane 32x272=8704; buf(hi+lo)=17408; ring-4
#define PLB  8704
#define BUFB 17408
#define SA   0
#define SA1  69632
#define SW   139264
#define SRED 208896
#define RSM  225280

// hgemm smem (bytes)
#define HA_L 18432
#define HB_H 36864
#define HB_L 46080
#define HBUF 55296
#define HSM  (2*HBUF)

// ---------------- device scratch ----------------
__device__ __align__(16) float g_gx0[(size_t)TT*BB*H2];   // [t][m][n]
__device__ __align__(16) float g_cx0[(size_t)TT*BB*H];
__device__ __align__(16) float g_outT[(size_t)TT*BB*H];
__device__ __align__(16) float g_h0m[2][BB*H];
__device__ __align__(16) float g_h1m[BB*H];
__device__ __align__(16) float g_u0m[BB*H];
__device__ __align__(16) float g_u1m[BB*H];
__device__ __align__(16) bf16 g_h0h[2][BB*H], g_h0l[2][BB*H];
__device__ __align__(16) bf16 g_h1h[BB*H],  g_h1l[BB*H];
__device__ __align__(16) bf16 g_rh0h[BB*H], g_rh0l[BB*H];
__device__ __align__(16) bf16 g_rh1h[BB*H], g_rh1l[BB*H];
__device__ __align__(16) bf16 g_wgt0h[(size_t)H2*H],  g_wgt0l[(size_t)H2*H];
__device__ __align__(16) bf16 g_wgt1h[(size_t)H2*H2], g_wgt1l[(size_t)H2*H2];
__device__ __align__(16) bf16 g_wct0h[(size_t)H*H],   g_wct0l[(size_t)H*H];
__device__ __align__(16) bf16 g_wct1h[(size_t)H*H2],  g_wct1l[(size_t)H*H2];
__device__ __align__(16) bf16 g_xh[(size_t)MROWS*H], g_xl[(size_t)MROWS*H];
__device__ __align__(16) bf16 g_oh[(size_t)MROWS*H], g_ol[(size_t)MROWS*H];
__device__ __align__(16) bf16 g_wgh[(size_t)H2*H],  g_wgl[(size_t)H2*H];
__device__ __align__(16) bf16 g_wch[(size_t)H*H],   g_wcl[(size_t)H*H];
__device__ __align__(16) bf16 g_eh[(size_t)VPAD*H], g_el[(size_t)VPAD*H];
__device__ volatile unsigned g_cnt;
__device__ volatile unsigned g_gen;

// ---------------- helpers ----------------
__device__ __forceinline__ float sigf(float x){ return __fdividef(1.f, 1.f+__expf(-x)); }
__device__ __forceinline__ float tanhx(float x){ return 1.f-__fdividef(2.f, __expf(2.f*x)+1.f); }

__device__ __forceinline__ void cp16(void* d, const void* s){
    unsigned ds = (unsigned)__cvta_generic_to_shared(d);
    asm volatile("cp.async.cg.shared.global [%0], [%1], 16;" :: "r"(ds), "l"(s) : "memory");
}
#define CP_COMMIT asm volatile("cp.async.commit_group;" ::: "memory")
#define CP_WAIT0  asm volatile("cp.async.wait_group 0;" ::: "memory")
#define CP_WAIT1  asm volatile("cp.async.wait_group 1;" ::: "memory")
#define CP_WAIT2  asm volatile("cp.async.wait_group 2;" ::: "memory")
__device__ __forceinline__ void cp_wait_rem(int rem){
    if (rem >= 2)      CP_WAIT2;
    else if (rem == 1) CP_WAIT1;
    else               CP_WAIT0;
}

__device__ __forceinline__ void gsync(){
    __threadfence();
    __syncthreads();
    if (threadIdx.x == 0){
        unsigned gen = g_gen;
        unsigned old = atomicAdd((unsigned*)&g_cnt, 1u);
        if (old == NB-1){ g_cnt = 0; __threadfence(); g_gen = gen+1; }
        else { while (g_gen == gen) { __nanosleep(40); } }
    }
    __syncthreads();
}

__device__ __forceinline__ void ldm4(unsigned& r0, unsigned& r1, unsigned& r2, unsigned& r3,
                                     unsigned addr){
    asm volatile("ldmatrix.sync.aligned.m8n8.x4.shared.b16 {%0,%1,%2,%3}, [%4];"
        : "=r"(r0), "=r"(r1), "=r"(r2), "=r"(r3) : "r"(addr));
}
__device__ __forceinline__ void mma16816(float* c, const unsigned* a, const unsigned* b){
    asm volatile("mma.sync.aligned.m16n8k16.row.col.f32.bf16.bf16.f32 "
        "{%0,%1,%2,%3},{%4,%5,%6,%7},{%8,%9},{%0,%1,%2,%3};"
        : "+f"(c[0]), "+f"(c[1]), "+f"(c[2]), "+f"(c[3])
        : "r"(a[0]), "r"(a[1]), "r"(a[2]), "r"(a[3]), "r"(b[0]), "r"(b[1]));
}
__device__ __forceinline__ void wsplit(float v, bf16* hp, bf16* lp, size_t o){
    bf16 h = __float2bfloat16(v);
    hp[o] = h; lp[o] = __float2bfloat16(v - __bfloat162float(h));
}

// ---------------- prep kernels ----------------
__global__ void prep_wq(const float* __restrict__ Wg0, const float* __restrict__ Wg1,
                        const float* __restrict__ Wc0, const float* __restrict__ Wc1){
    __shared__ float s[32][33];
    int b = blockIdx.x;
    const float* src; bf16 *dh, *dl; int srow0, ld, ldd, bx, by;
    if (b < 2048){      src=Wg0; srow0=1024; ld=H2; dh=g_wgt0h; dl=g_wgt0l; ldd=H;  bx=b&31; by=b>>5; }
    else if (b<6144){ int q=b-2048; src=Wg1; srow0=0; ld=H2; dh=g_wgt1h; dl=g_wgt1l; ldd=H2; bx=q&63; by=q>>6; }
    else if (b<7168){ int q=b-6144; src=Wc0; srow0=1024; ld=H; dh=g_wct0h; dl=g_wct0l; ldd=H; bx=q&31; by=q>>5; }
    else {            int q=b-7168; src=Wc1; srow0=0; ld=H; dh=g_wct1h; dl=g_wct1l; ldd=H2; bx=q&63; by=q>>6; }
    int kb = bx*32, nb = by*32;
    int t = threadIdx.x, tx = t&31, ty = t>>5;
#pragma unroll
    for (int i=0;i<32;i+=8) s[ty+i][tx] = src[(size_t)(srow0+kb+ty+i)*ld + nb+tx];
    __syncthreads();
#pragma unroll
    for (int i=0;i<32;i+=8)
        wsplit(s[tx][ty+i], dh, dl, (size_t)(nb+ty+i)*ldd + kb+tx);
}

__global__ void prep_cv(const int* __restrict__ idx, const float* __restrict__ emb,
                        const float* __restrict__ Wg0, const float* __restrict__ Wc0){
    __shared__ float s[32][33];
    int b = blockIdx.x, t = threadIdx.x;
    if (b < 4096){
        float4 v = ((const float4*)(emb + (size_t)idx[b]*H))[t];
        float a[4] = {v.x,v.y,v.z,v.w};
        size_t o = (size_t)b*H + t*4;
#pragma unroll
        for (int j=0;j<4;j++) wsplit(a[j], g_xh, g_xl, o+j);
    } else if (b < 7168){
        const float* src; bf16 *hi, *lo; int ld, kb, nb;
        if (b < 6144){ int q=b-4096; src=Wg0; ld=H2; hi=g_wgh; lo=g_wgl; kb=(q&31)*32; nb=(q>>5)*32; }
        else         { int q=b-6144; src=Wc0; ld=H;  hi=g_wch; lo=g_wcl; kb=(q&31)*32; nb=(q>>5)*32; }
        int tx = t&31, ty = t>>5;
#pragma unroll
        for (int i=0;i<32;i+=8) s[ty+i][tx] = src[(size_t)(kb+ty+i)*ld + nb+tx];
        __syncthreads();
#pragma unroll
        for (int i=0;i<32;i+=8)
            wsplit(s[tx][ty+i], hi, lo, (size_t)(nb+ty+i)*H + kb+tx);
    } else {
        int row = b - 7168;
        size_t o = (size_t)row*H + t*4;
        if (row < VOCAB){
            float4 v = ((const float4*)(emb + (size_t)row*H))[t];
            float a[4] = {v.x,v.y,v.z,v.w};
#pragma unroll
            for (int j=0;j<4;j++) wsplit(a[j], g_eh, g_el, o+j);
        } else {
#pragma unroll
            for (int j=0;j<4;j++){ g_eh[o+j]=__float2bfloat16(0.f); g_el[o+j]=__float2bfloat16(0.f); }
        }
    }
}

__global__ void outconv(const float* __restrict__ outT){
    int r = blockIdx.x, tid = threadIdx.x;
    int m = r>>7, t = r&127;
    float4 v = ((const float4*)(outT + ((size_t)t*BB + m)*H))[tid];
    float a[4] = {v.x,v.y,v.z,v.w};
    size_t o = (size_t)r*H + tid*4;
#pragma unroll
    for (int j=0;j<4;j++) wsplit(a[j], g_oh, g_ol, o+j);
}

// ---------------- HMMA bf16-split big GEMM (proven) ----------------
template<bool GRUL>
__global__ void __launch_bounds__(256, 2)
hgemm(const bf16* __restrict__ Ah, const bf16* __restrict__ Al,
      const bf16* __restrict__ Bh, const bf16* __restrict__ Bl,
      const float* __restrict__ bias, float* __restrict__ C, int N)
{
    extern __shared__ __align__(16) char smc[];
    const int tid = threadIdx.x, wid = tid>>5, lane = tid&31;
    const int n0 = blockIdx.x*64, m0 = blockIdx.y*128;
    const int wm = wid&3, wn = wid>>2;
    unsigned sb = (unsigned)__cvta_generic_to_shared(smc);

    auto stage = [&](int kc){
        char* base = smc + (kc&1)*HBUF;
#pragma unroll
        for (int u=0;u<8;u++){
            int e = tid + u*256;
            int pl = e>>10, i = e&1023, row = i>>3, g = i&7;
            const bf16* src = (pl?Al:Ah) + (size_t)(m0+row)*H + kc*64 + g*8;
            cp16(base + (pl?HA_L:0) + row*144 + g*16, src);
        }
#pragma unroll
        for (int u=0;u<4;u++){
            int e = tid + u*256;
            int pl = e>>9, i = e&511, row = i>>3, g = i&7;
            const bf16* src = (pl?Bl:Bh) + (size_t)(n0+row)*H + kc*64 + g*8;
            cp16(base + (pl?HB_L:HB_H) + row*144 + g*16, src);
        }
    };

    float cc[2][4][4];
#pragma unroll
    for (int a=0;a<2;a++)
#pragma unroll
        for (int b=0;b<4;b++)
#pragma unroll
            for (int q=0;q<4;q++) cc[a][b][q] = 0.f;

    stage(0); CP_COMMIT;
    for (int kc=0;kc<16;kc++){
        if (kc < 15){ stage(kc+1); CP_COMMIT; CP_WAIT1; } else CP_WAIT0;
        __syncthreads();
        unsigned bufb = sb + (kc&1)*HBUF;
        unsigned aB = bufb + (wm*32 + (lane&15))*144 + ((lane>>4)&1)*16;
        unsigned bB = bufb + HB_H + (wn*32 + (lane&7) + ((lane>>4)&1)*8)*144 + ((lane>>3)&1)*16;
#pragma unroll
        for (int ks=0;ks<4;ks++){
            unsigned ah[8], al[8], bh[8], bl[8];
            ldm4(ah[0],ah[1],ah[2],ah[3], aB + ks*32);
            ldm4(ah[4],ah[5],ah[6],ah[7], aB + 16*144 + ks*32);
            ldm4(al[0],al[1],al[2],al[3], aB + HA_L + ks*32);
            ldm4(al[4],al[5],al[6],al[7], aB + HA_L + 16*144 + ks*32);
            ldm4(bh[0],bh[1],bh[2],bh[3], bB + ks*32);
            ldm4(bh[4],bh[5],bh[6],bh[7], bB + 16*144 + ks*32);
            ldm4(bl[0],bl[1],bl[2],bl[3], bB + (HB_L-HB_H) + ks*32);
            ldm4(bl[4],bl[5],bl[6],bl[7], bB + (HB_L-HB_H) + 16*144 + ks*32);
#pragma unroll
            for (int fm=0;fm<2;fm++)
#pragma unroll
                for (int fn=0;fn<4;fn++){
                    mma16816(cc[fm][fn], ah+fm*4, bh+fn*2);
                    mma16816(cc[fm][fn], ah+fm*4, bl+fn*2);
                    mma16816(cc[fm][fn], al+fm*4, bh+fn*2);
                }
        }
        __syncthreads();
    }

    const int rb = lane>>2, cb = (lane&3)*2;
#pragma unroll
    for (int fm=0;fm<2;fm++){
#pragma unroll
        for (int half=0;half<2;half++){
            int r = m0 + wm*32 + fm*16 + rb + half*8;
            int r2 = GRUL ? ((r & 127)*BB + (r >> 7)) : r;
            float* crow = C + (size_t)r2*N;
#pragma unroll
            for (int fn=0;fn<4;fn++){
                int n = n0 + wn*32 + fn*8 + cb;
                if (n < N){
                    float2 v;
                    v.x = cc[fm][fn][half*2+0];
                    v.y = cc[fm][fn][half*2+1];
                    if (bias){
                        float2 b = *(const float2*)(bias + n);
                        v.x += b.x; v.y += b.y;
                    }
                    *(float2*)(crow + n) = v;
                }
            }
        }
    }
}

// ---------------- persistent HMMA recurrence (chunk=128, ring-4, 512 thr) ----------------
__global__ void __launch_bounds__(NTHR, 1)
rnn_persist(const float* __restrict__ bg0, const float* __restrict__ bc0,
            const float* __restrict__ bg1, const float* __restrict__ bc1)
{
    extern __shared__ __align__(16) char smc[];
    const int tid = threadIdx.x, c = blockIdx.x;
    const int lane = tid & 31, w = tid >> 5;
    unsigned sb = (unsigned)__cvta_generic_to_shared(smc);
    float* redf = (float*)(smc + SRED);

    for (int i = c*NTHR+tid; i < BB*H; i += NB*NTHR){
        bf16 z = __float2bfloat16(0.f);
        g_h0m[0][i]=0.f; g_h1m[i]=0.f;
        g_h0h[0][i]=z; g_h0l[0][i]=z; g_h1h[i]=z; g_h1l[i]=z;
    }
    gsync();

    // phase A: ngA(4) x mA(2) x ksA(2);  phase B: lB(2) x mB(2) x ksB(4)
    const int ngA = w & 3, mA = (w>>2)&1, ksA = w>>3;
    const int lB = w & 1, mB = (w>>1)&1, ksB = w>>2;

    int cur = 0;
    for (int t = 0; t <= TT; t++){
        const bool do0 = (t < TT), do1 = (t > 0);
        const int nc = do1 ? 16 : 8;

        // ===================== PHASE A: gates =====================
        {
            auto stage = [&](int kc){
                int bi = kc & 3;
                char* Ab = smc + SA + bi*BUFB;
                const bf16 *sh, *sl; int ko;
                if (kc < 8){ sh = g_h0h[cur]; sl = g_h0l[cur]; ko = kc*128; }
                else       { sh = g_h1h;      sl = g_h1l;      ko = (kc-8)*128; }
                {   int row = tid>>4, g = tid&15;
                    cp16(Ab + row*272 + g*16,       sh + (size_t)row*H + ko + g*8);
                    cp16(Ab + PLB + row*272 + g*16, sl + (size_t)row*H + ko + g*8);
                }
                char* Wb = smc + SW + bi*BUFB;
                {   int r = tid>>4, g = tid&15;
                    if (r >= 16){
                        size_t o1 = (size_t)(c*16 + r-16)*H2 + kc*128 + g*8;
                        cp16(Wb + r*272 + g*16,       g_wgt1h + o1);
                        cp16(Wb + PLB + r*272 + g*16, g_wgt1l + o1);
                    } else if (kc < 8){
                        size_t o0 = (size_t)(c*16 + r)*H + kc*128 + g*8;
                        cp16(Wb + r*272 + g*16,       g_wgt0h + o0);
                        cp16(Wb + PLB + r*272 + g*16, g_wgt0l + o0);
                    }
                }
                CP_COMMIT;
            };
            stage(0); stage(1); stage(2);
            float c0[4], c1[4], c2[4];
            #pragma unroll
            for (int q=0;q<4;q++){ c0[q]=0.f; c1[q]=0.f; c2[q]=0.f; }

            for (int kc=0;kc<nc;kc++){
                cp_wait_rem(nc-1-kc);
                __syncthreads();
                if (kc+3 < nc) stage(kc+3);
                const bool act = (ngA < 2) ? (do0 && kc < 8) : do1;
                if (act){
                    int bi = kc & 3;
                    unsigned sA = sb + SA + bi*BUFB;
                    unsigned sW = sb + SW + bi*BUFB;
                    unsigned wB = sW + (ngA*8 + (lane&7))*272 + ((lane>>3)&3)*16 + ksA*128;
                    unsigned bh[8], bl[8];
                    ldm4(bh[0],bh[1],bh[2],bh[3], wB);
                    ldm4(bh[4],bh[5],bh[6],bh[7], wB + 64);
                    ldm4(bl[0],bl[1],bl[2],bl[3], wB + PLB);
                    ldm4(bl[4],bl[5],bl[6],bl[7], wB + PLB + 64);
                    unsigned aB = sA + (mA*16 + (lane&15))*272 + ((lane>>4)&1)*16 + ksA*128;
                    #pragma unroll
                    for (int s=0;s<4;s++){
                        unsigned ah[4], al[4];
                        ldm4(ah[0],ah[1],ah[2],ah[3], aB + s*32);
                        ldm4(al[0],al[1],al[2],al[3], aB + PLB + s*32);
                        mma16816(c0, ah, bh+2*s);
                        mma16816(c1, ah, bl+2*s);
                        mma16816(c2, al, bh+2*s);
                    }
                }
            }
            __syncthreads();
            #pragma unroll
            for (int q=0;q<4;q++){
                int m = mA*16 + (lane>>2) + (q>>1)*8;
                int nl = (lane&3)*2 + (q&1);
                redf[(w*32 + m)*8 + nl] = c0[q]+c1[q]+c2[q];
            }
            __syncthreads();
            #pragma unroll
            for (int u=0;u<2;u++){
                int o = tid + u*NTHR;
                int m = o>>5, col = o&31;
                int ng2 = col>>3, nl = col&7;
                int w0 = (m>>4)*4 + ng2;
                float s = redf[(w0*32+m)*8+nl] + redf[((8+w0)*32+m)*8+nl];
                if (col < 16){
                    if (do0){
                        int n = c*16 + col;
                        s += g_gx0[((size_t)t*BB+m)*H2 + n] + bg0[n];
                        float g = sigf(s);
                        if (n < H){
                            float v = g * g_h0m[cur][m*H+n];
                            wsplit(v, g_rh0h, g_rh0l, (size_t)m*H + n);
                        } else g_u0m[m*H + n-H] = g;
                    }
                } else {
                    if (do1){
                        int n = c*16 + col - 16;
                        s += bg1[n];
                        float g = sigf(s);
                        if (n < H){
                            float v = g * g_h1m[m*H+n];
                            wsplit(v, g_rh1h, g_rh1l, (size_t)m*H + n);
                        } else g_u1m[m*H + n-H] = g;
                    }
                }
            }
        }
        gsync();

        // ===================== PHASE B: candidates + update =====================
        {
            auto stage = [&](int kc){
                int bi = kc & 3;
                char* A1b = smc + SA1 + bi*BUFB;
                const bf16 *sh, *sl; int ko;
                if (kc < 8){ sh = g_h0h[cur]; sl = g_h0l[cur]; ko = kc*128; }
                else       { sh = g_rh1h;     sl = g_rh1l;     ko = (kc-8)*128; }
                {   int row = tid>>4, g = tid&15;
                    cp16(A1b + row*272 + g*16,       sh + (size_t)row*H + ko + g*8);
                    cp16(A1b + PLB + row*272 + g*16, sl + (size_t)row*H + ko + g*8);
                }
                if (kc < 8){
                    char* A0b = smc + SA + bi*BUFB;
                    int row = tid>>4, g = tid&15;
                    cp16(A0b + row*272 + g*16,       g_rh0h + (size_t)row*H + kc*128 + g*8);
                    cp16(A0b + PLB + row*272 + g*16, g_rh0l + (size_t)row*H + kc*128 + g*8);
                }
                char* Wb = smc + SW + bi*BUFB;
                if (tid < 256){
                    int r = tid>>4, g = tid&15;
                    if (r >= 8){
                        size_t o1 = (size_t)(c*8 + r-8)*H2 + kc*128 + g*8;
                        cp16(Wb + r*272 + g*16,       g_wct1h + o1);
                        cp16(Wb + PLB + r*272 + g*16, g_wct1l + o1);
                    } else if (kc < 8){
                        size_t o0 = (size_t)(c*8 + r)*H + kc*128 + g*8;
                        cp16(Wb + r*272 + g*16,       g_wct0h + o0);
                        cp16(Wb + PLB + r*272 + g*16, g_wct0l + o0);
                    }
                }
                CP_COMMIT;
            };
            stage(0); stage(1); stage(2);
            float c0[4], c1[4], c2[4];
            #pragma unroll
            for (int q=0;q<4;q++){ c0[q]=0.f; c1[q]=0.f; c2[q]=0.f; }

            for (int kc=0;kc<nc;kc++){
                cp_wait_rem(nc-1-kc);
                __syncthreads();
                if (kc+3 < nc) stage(kc+3);
                const bool act = (lB == 0) ? (do0 && kc < 8) : do1;
                if (act){
                    int bi = kc & 3;
                    unsigned sAx = sb + (lB ? SA1 : SA) + bi*BUFB;
                    unsigned sW = sb + SW + bi*BUFB;
                    unsigned wB = sW + (lB*8 + (lane&7))*272 + ((lane>>3)&3)*16 + ksB*64;
                    unsigned bh[4], bl[4];
                    ldm4(bh[0],bh[1],bh[2],bh[3], wB);
                    ldm4(bl[0],bl[1],bl[2],bl[3], wB + PLB);
                    unsigned aB = sAx + (mB*16 + (lane&15))*272 + ((lane>>4)&1)*16 + ksB*64;
                    #pragma unroll
                    for (int s=0;s<2;s++){
                        unsigned ah[4], al[4];
                        ldm4(ah[0],ah[1],ah[2],ah[3], aB + s*32);
                        ldm4(al[0],al[1],al[2],al[3], aB + PLB + s*32);
                        mma16816(c0, ah, bh+2*s);
                        mma16816(c1, ah, bl+2*s);
                        mma16816(c2, al, bh+2*s);
                    }
                }
            }
            __syncthreads();
            #pragma unroll
            for (int q=0;q<4;q++){
                int m = mB*16 + (lane>>2) + (q>>1)*8;
                int nl = (lane&3)*2 + (q&1);
                redf[(w*32 + m)*8 + nl] = c0[q]+c1[q]+c2[q];
            }
            __syncthreads();
            {
                int o = tid;
                int m = o>>4, col = o&15;
                int lg = col>>3, nl = col&7;
                int w0 = (m>>4)*2 + lg;
                float s = redf[((0*4+w0)*32+m)*8+nl] + redf[((1*4+w0)*32+m)*8+nl]
                        + redf[((2*4+w0)*32+m)*8+nl] + redf[((3*4+w0)*32+m)*8+nl];
                if (lg == 0){
                    if (do0){
                        int n = c*8 + nl;
                        s += g_cx0[((size_t)t*BB+m)*H + n] + bc0[n];
                        float cc = tanhx(s);
                        float uu = g_u0m[m*H+n];
                        float hn = uu * g_h0m[cur][m*H+n] + (1.f-uu)*cc;
                        g_h0m[cur^1][m*H+n] = hn;
                        wsplit(hn, g_h0h[cur^1], g_h0l[cur^1], (size_t)m*H + n);
                    }
                } else {
                    if (do1){
                        int n = c*8 + nl;
                        s += bc1[n];
                        float cc = tanhx(s);
                        float uu = g_u1m[m*H+n];
                        float hn = uu * g_h1m[m*H+n] + (1.f-uu)*cc;
                        g_h1m[m*H+n] = hn;
                        wsplit(hn, g_h1h, g_h1l, (size_t)m*H + n);
                        g_outT[((size_t)(t-1)*BB+m)*H + n] = hn;
                    }
                }
            }
        }
        cur ^= 1;
        gsync();
    }
}

// ---------------- launch ----------------
extern "C" void kernel_launch(void* const* d_in, const int* in_sizes, int n_in,
                              void* d_out, int out_size)
{
    const int*   idx = (const int*)  d_in[0];
    const float* emb = (const float*)d_in[1];
    const float* Wg0 = (const float*)d_in[2];
    const float* bg0 = (const float*)d_in[3];
    const float* Wc0 = (const float*)d_in[4];
    const float* bc0 = (const float*)d_in[5];
    const float* Wg1 = (const float*)d_in[6];
    const float* bg1 = (const float*)d_in[7];
    const float* Wc1 = (const float*)d_in[8];
    const float* bc1 = (const float*)d_in[9];
    const float* smb = (const float*)d_in[10];
    float* out = (float*)d_out;

    float *pgx0,*pcx0,*poutT;
    bf16 *pxh,*pxl,*poh,*pol,*pwgh,*pwgl,*pwch,*pwcl,*peh,*pel;
    cudaGetSymbolAddress((void**)&pgx0,  g_gx0);
    cudaGetSymbolAddress((void**)&pcx0,  g_cx0);
    cudaGetSymbolAddress((void**)&poutT, g_outT);
    cudaGetSymbolAddress((void**)&pxh,   g_xh);
    cudaGetSymbolAddress((void**)&pxl,   g_xl);
    cudaGetSymbolAddress((void**)&poh,   g_oh);
    cudaGetSymbolAddress((void**)&pol,   g_ol);
    cudaGetSymbolAddress((void**)&pwgh,  g_wgh);
    cudaGetSymbolAddress((void**)&pwgl,  g_wgl);
    cudaGetSymbolAddress((void**)&pwch,  g_wch);
    cudaGetSymbolAddress((void**)&pwcl,  g_wcl);
    cudaGetSymbolAddress((void**)&peh,   g_eh);
    cudaGetSymbolAddress((void**)&pel,   g_el);

    static bool attr_set = false;
    if (!attr_set){
        cudaFuncSetAttribute(rnn_persist, cudaFuncAttributeMaxDynamicSharedMemorySize, RSM);
        cudaFuncSetAttribute(hgemm<true>,  cudaFuncAttributeMaxDynamicSharedMemorySize, HSM);
        cudaFuncSetAttribute(hgemm<false>, cudaFuncAttributeMaxDynamicSharedMemorySize, HSM);
        attr_set = true;
    }

    prep_wq<<<9216, 256>>>(Wg0, Wg1, Wc0, Wc1);
    prep_cv<<<7168 + VPAD, 256>>>(idx, emb, Wg0, Wc0);

    hgemm<true><<<dim3(H2/64, MROWS/128), 256, HSM>>>(pxh, pxl, pwgh, pwgl, nullptr, pgx0, H2);
    hgemm<true><<<dim3(H/64,  MROWS/128), 256, HSM>>>(pxh, pxl, pwch, pwcl, nullptr, pcx0, H);

    rnn_persist<<<NB, NTHR, RSM>>>(bg0, bc0, bg1, bc1);

    outconv<<<MROWS, 256>>>(poutT);
    hgemm<false><<<dim3(VPAD/64, MROWS/128), 256, HSM>>>(poh, pol, peh, pel, smb, out, VOCAB);
}